// round 1
// baseline (speedup 1.0000x reference)
#include <cuda_runtime.h>
#include <math.h>

#define BB 4
#define SS 2048
#define DD 2048
#define HH 16
#define HD 128
#define MM (BB*SS)   // 8192

// Scratch (device globals: allocation-free rule)
__device__ float g_q[(size_t)BB*HH*SS*HD];
__device__ float g_k[(size_t)BB*HH*SS*HD];
__device__ float g_v[(size_t)BB*HH*SS*HD];
__device__ float g_ctx[(size_t)MM*DD];
__device__ float g_cos[SS*64];
__device__ float g_sin[SS*64];

// ---------------------------------------------------------------------------
// RoPE cos/sin table: matches reference fp32 formulation
// inv_freq[p] = 10000^(-p/64), angle = s * inv_freq (fp32 product)
// ---------------------------------------------------------------------------
__global__ void rope_table_kernel() {
    int idx = blockIdx.x * blockDim.x + threadIdx.x;
    if (idx >= SS * 64) return;
    int s = idx >> 6, p = idx & 63;
    double invf = exp(-(double)p * (log(10000.0) / 64.0));
    float ang = (float)s * (float)invf;
    float sv, cv;
    sincosf(ang, &sv, &cv);
    g_cos[idx] = cv;
    g_sin[idx] = sv;
}

// ---------------------------------------------------------------------------
// GEMM: C[m,n] = sum_k A[m,k] * W[n,k]   (A:[M,K] row-major, W:[N,K] row-major)
// 128x128 block tile, BK=16, 256 threads, 8x8 per-thread micro-tile.
// MODE 0: plain output [M,N] + bias
// MODE 1: heads layout  out[((b*H+h)*S+s)*HD + d]
// MODE 2: heads layout + RoPE in epilogue
// ---------------------------------------------------------------------------
template<int MODE>
__global__ void __launch_bounds__(256) gemm_nt_kernel(
    const float* __restrict__ A, const float* __restrict__ W,
    const float* __restrict__ bias, float* __restrict__ C)
{
    __shared__ float As[16][132];
    __shared__ float Bs[16][132];

    int tid = threadIdx.x;
    int ty = tid >> 4, tx = tid & 15;
    int rowA0 = blockIdx.y * 128;
    int rowB0 = blockIdx.x * 128;

    float acc[8][8];
#pragma unroll
    for (int i = 0; i < 8; i++)
#pragma unroll
        for (int j = 0; j < 8; j++) acc[i][j] = 0.f;

    const float* Aptr = A + (size_t)rowA0 * DD;
    const float* Wptr = W + (size_t)rowB0 * DD;

    for (int kt = 0; kt < DD; kt += 16) {
#pragma unroll
        for (int l = 0; l < 2; l++) {
            int f = tid + l * 256;         // 0..511
            int r = f >> 2;                 // 0..127
            int k4 = (f & 3) << 2;          // 0,4,8,12
            float4 va = *(const float4*)&Aptr[(size_t)r * DD + kt + k4];
            As[k4 + 0][r] = va.x; As[k4 + 1][r] = va.y;
            As[k4 + 2][r] = va.z; As[k4 + 3][r] = va.w;
            float4 vb = *(const float4*)&Wptr[(size_t)r * DD + kt + k4];
            Bs[k4 + 0][r] = vb.x; Bs[k4 + 1][r] = vb.y;
            Bs[k4 + 2][r] = vb.z; Bs[k4 + 3][r] = vb.w;
        }
        __syncthreads();
#pragma unroll
        for (int kk = 0; kk < 16; kk++) {
            float4 a0 = *(const float4*)&As[kk][ty * 8];
            float4 a1 = *(const float4*)&As[kk][ty * 8 + 4];
            float4 b0 = *(const float4*)&Bs[kk][tx * 8];
            float4 b1 = *(const float4*)&Bs[kk][tx * 8 + 4];
            float av[8] = {a0.x, a0.y, a0.z, a0.w, a1.x, a1.y, a1.z, a1.w};
            float bv[8] = {b0.x, b0.y, b0.z, b0.w, b1.x, b1.y, b1.z, b1.w};
#pragma unroll
            for (int i = 0; i < 8; i++)
#pragma unroll
                for (int j = 0; j < 8; j++)
                    acc[i][j] = fmaf(av[i], bv[j], acc[i][j]);
        }
        __syncthreads();
    }

    if (MODE == 0) {
#pragma unroll
        for (int i = 0; i < 8; i++) {
            int m = rowA0 + ty * 8 + i;
            int n0 = rowB0 + tx * 8;
            float4 o0, o1;
            o0.x = acc[i][0] + bias[n0 + 0];
            o0.y = acc[i][1] + bias[n0 + 1];
            o0.z = acc[i][2] + bias[n0 + 2];
            o0.w = acc[i][3] + bias[n0 + 3];
            o1.x = acc[i][4] + bias[n0 + 4];
            o1.y = acc[i][5] + bias[n0 + 5];
            o1.z = acc[i][6] + bias[n0 + 6];
            o1.w = acc[i][7] + bias[n0 + 7];
            *(float4*)&C[(size_t)m * DD + n0] = o0;
            *(float4*)&C[(size_t)m * DD + n0 + 4] = o1;
        }
    } else {
        int h = blockIdx.x;   // 128-wide N tile == head
#pragma unroll
        for (int i = 0; i < 8; i++) {
            int m = rowA0 + ty * 8 + i;
            int b = m / SS, s = m % SS;
            float vals[8];
#pragma unroll
            for (int j = 0; j < 8; j++) vals[j] = acc[i][j];
            if (MODE == 2) {
#pragma unroll
                for (int j = 0; j < 8; j += 2) {
                    int d = tx * 8 + j;
                    int p = d >> 1;
                    float cv = g_cos[s * 64 + p];
                    float sn = g_sin[s * 64 + p];
                    float t1 = vals[j], t2 = vals[j + 1];
                    vals[j]     = t1 * cv - t2 * sn;
                    vals[j + 1] = t1 * sn + t2 * cv;
                }
            }
            float* outp = C + (((size_t)(b * HH + h) * SS + s) * HD + tx * 8);
            float4 w0 = {vals[0], vals[1], vals[2], vals[3]};
            float4 w1 = {vals[4], vals[5], vals[6], vals[7]};
            *(float4*)&outp[0] = w0;
            *(float4*)&outp[4] = w1;
        }
    }
}

// ---------------------------------------------------------------------------
// Flash attention, causal. BM=64 q rows per CTA, BN=128 k cols per tile.
// 256 threads: 16x16 grid, 4 rows x 8 cols per thread.
// Layouts: Q/K/V [B][H][S][HD]; CTX written as (B,S,H,HD) == (B,S,D).
// ---------------------------------------------------------------------------
#define QPAD 132
#define KPAD 136
#define PPAD 132
#define ATTN_SMEM_FLOATS (64*QPAD + 128*KPAD + 128*128 + 64*PPAD)
#define ATTN_SMEM_BYTES  (ATTN_SMEM_FLOATS * 4)

__global__ void __launch_bounds__(256) attn_kernel(
    const float* __restrict__ Q, const float* __restrict__ K,
    const float* __restrict__ V, float* __restrict__ CTX)
{
    extern __shared__ float sm[];
    float* Qs  = sm;                  // [64][132] row-major
    float* KsT = Qs + 64 * QPAD;      // [128][136] d-major (transposed)
    float* Vs  = KsT + 128 * KPAD;    // [128][128] row-major
    float* Ps  = Vs + 128 * 128;      // [64][132]

    int tid = threadIdx.x;
    int ty = tid >> 4, tx = tid & 15;
    int bh = blockIdx.y;
    int b = bh / HH, h = bh % HH;
    int q0 = blockIdx.x * 64;

    const float* Qb = Q + (size_t)bh * SS * HD;
    const float* Kb = K + (size_t)bh * SS * HD;
    const float* Vb = V + (size_t)bh * SS * HD;

    // Load Q tile [64][128]
#pragma unroll
    for (int l = 0; l < 8; l++) {
        int f = tid + l * 256;          // 0..2047
        int r = f >> 5;
        int d = (f & 31) << 2;
        *(float4*)&Qs[r * QPAD + d] = *(const float4*)&Qb[(size_t)(q0 + r) * HD + d];
    }

    float mreg[4], lreg[4], o[4][8];
#pragma unroll
    for (int i = 0; i < 4; i++) {
        mreg[i] = -1e30f; lreg[i] = 0.f;
#pragma unroll
        for (int j = 0; j < 8; j++) o[i][j] = 0.f;
    }

    const float scale = 0.08838834764831845f;  // 1/sqrt(128)
    int nkt = q0 / 128 + 1;

    for (int kt = 0; kt < nkt; kt++) {
        int k0 = kt * 128;
        __syncthreads();   // previous iteration done with KsT/Vs/Ps
        // Load K tile transposed: KsT[d][c]
#pragma unroll
        for (int l = 0; l < 16; l++) {
            int f = tid + l * 256;       // 0..4095
            int c = f & 127;
            int d = (f >> 7) << 2;
            float4 v = *(const float4*)&Kb[(size_t)(k0 + c) * HD + d];
            KsT[(d + 0) * KPAD + c] = v.x;
            KsT[(d + 1) * KPAD + c] = v.y;
            KsT[(d + 2) * KPAD + c] = v.z;
            KsT[(d + 3) * KPAD + c] = v.w;
        }
        // Load V tile row-major
#pragma unroll
        for (int l = 0; l < 16; l++) {
            int f = tid + l * 256;
            int r = f >> 5;
            int d = (f & 31) << 2;
            *(float4*)&Vs[r * 128 + d] = *(const float4*)&Vb[(size_t)(k0 + r) * HD + d];
        }
        __syncthreads();

        // S = Q @ K^T  (64 x 128 tile)
        float sv[4][8];
#pragma unroll
        for (int i = 0; i < 4; i++)
#pragma unroll
            for (int j = 0; j < 8; j++) sv[i][j] = 0.f;

#pragma unroll 2
        for (int d = 0; d < 128; d += 4) {
            float4 q4[4];
#pragma unroll
            for (int i = 0; i < 4; i++)
                q4[i] = *(const float4*)&Qs[(ty * 4 + i) * QPAD + d];
#pragma unroll
            for (int u = 0; u < 4; u++) {
                float4 ka = *(const float4*)&KsT[(d + u) * KPAD + tx * 8];
                float4 kb2 = *(const float4*)&KsT[(d + u) * KPAD + tx * 8 + 4];
                float kv[8] = {ka.x, ka.y, ka.z, ka.w, kb2.x, kb2.y, kb2.z, kb2.w};
#pragma unroll
                for (int i = 0; i < 4; i++) {
                    float qv = (u == 0) ? q4[i].x : (u == 1) ? q4[i].y
                             : (u == 2) ? q4[i].z : q4[i].w;
#pragma unroll
                    for (int j = 0; j < 8; j++)
                        sv[i][j] = fmaf(qv, kv[j], sv[i][j]);
                }
            }
        }

        // Online softmax (per-row state replicated in registers across tx)
        bool last = (kt == nkt - 1);
#pragma unroll
        for (int i = 0; i < 4; i++) {
            int rg = q0 + ty * 4 + i;
            float rmax = -1e30f;
#pragma unroll
            for (int j = 0; j < 8; j++) {
                float xv = sv[i][j] * scale;
                if (last && (k0 + tx * 8 + j > rg)) xv = -1e30f;
                sv[i][j] = xv;
                rmax = fmaxf(rmax, xv);
            }
#pragma unroll
            for (int off = 8; off; off >>= 1)
                rmax = fmaxf(rmax, __shfl_xor_sync(0xffffffffu, rmax, off));
            float mnew = fmaxf(mreg[i], rmax);
            float al = __expf(mreg[i] - mnew);
            float rs = 0.f;
#pragma unroll
            for (int j = 0; j < 8; j++) {
                float p = __expf(sv[i][j] - mnew);
                sv[i][j] = p;
                rs += p;
            }
#pragma unroll
            for (int off = 8; off; off >>= 1)
                rs += __shfl_xor_sync(0xffffffffu, rs, off);
            lreg[i] = lreg[i] * al + rs;
            mreg[i] = mnew;
#pragma unroll
            for (int j = 0; j < 8; j++) o[i][j] *= al;
        }

        // Store P
#pragma unroll
        for (int i = 0; i < 4; i++) {
            float4 p0 = {sv[i][0], sv[i][1], sv[i][2], sv[i][3]};
            float4 p1 = {sv[i][4], sv[i][5], sv[i][6], sv[i][7]};
            *(float4*)&Ps[(ty * 4 + i) * PPAD + tx * 8] = p0;
            *(float4*)&Ps[(ty * 4 + i) * PPAD + tx * 8 + 4] = p1;
        }
        __syncthreads();

        // O += P @ V
#pragma unroll 2
        for (int kk = 0; kk < 128; kk += 4) {
            float4 p4[4];
#pragma unroll
            for (int i = 0; i < 4; i++)
                p4[i] = *(const float4*)&Ps[(ty * 4 + i) * PPAD + kk];
#pragma unroll
            for (int u = 0; u < 4; u++) {
                float4 va = *(const float4*)&Vs[(kk + u) * 128 + tx * 8];
                float4 vb = *(const float4*)&Vs[(kk + u) * 128 + tx * 8 + 4];
                float vv[8] = {va.x, va.y, va.z, va.w, vb.x, vb.y, vb.z, vb.w};
#pragma unroll
                for (int i = 0; i < 4; i++) {
                    float pw = (u == 0) ? p4[i].x : (u == 1) ? p4[i].y
                             : (u == 2) ? p4[i].z : p4[i].w;
#pragma unroll
                    for (int j = 0; j < 8; j++)
                        o[i][j] = fmaf(pw, vv[j], o[i][j]);
                }
            }
        }
    }

    // Normalize and write ctx in (B,S,H,HD) layout
#pragma unroll
    for (int i = 0; i < 4; i++) {
        float inv = 1.f / lreg[i];
        int r = q0 + ty * 4 + i;
        float* dst = CTX + ((size_t)(b * SS + r) * DD + h * HD + tx * 8);
        float4 w0 = {o[i][0] * inv, o[i][1] * inv, o[i][2] * inv, o[i][3] * inv};
        float4 w1 = {o[i][4] * inv, o[i][5] * inv, o[i][6] * inv, o[i][7] * inv};
        *(float4*)&dst[0] = w0;
        *(float4*)&dst[4] = w1;
    }
}

// ---------------------------------------------------------------------------
extern "C" void kernel_launch(void* const* d_in, const int* in_sizes, int n_in,
                              void* d_out, int out_size)
{
    const float* x  = (const float*)d_in[0];
    const float* wq = (const float*)d_in[1];
    const float* wk = (const float*)d_in[2];
    const float* wv = (const float*)d_in[3];
    const float* wo = (const float*)d_in[4];
    const float* bo = (const float*)d_in[5];
    float* out = (float*)d_out;

    float *qp, *kp, *vp, *cp;
    cudaGetSymbolAddress((void**)&qp, g_q);
    cudaGetSymbolAddress((void**)&kp, g_k);
    cudaGetSymbolAddress((void**)&vp, g_v);
    cudaGetSymbolAddress((void**)&cp, g_ctx);

    // RoPE tables (cheap, recomputed each call for determinism)
    rope_table_kernel<<<(SS * 64 + 255) / 256, 256>>>();

    dim3 ggrid(DD / 128, MM / 128);   // (16, 64)
    gemm_nt_kernel<2><<<ggrid, 256>>>(x, wq, nullptr, qp);   // Q + RoPE
    gemm_nt_kernel<2><<<ggrid, 256>>>(x, wk, nullptr, kp);   // K + RoPE
    gemm_nt_kernel<1><<<ggrid, 256>>>(x, wv, nullptr, vp);   // V

    cudaFuncSetAttribute(attn_kernel,
                         cudaFuncAttributeMaxDynamicSharedMemorySize,
                         ATTN_SMEM_BYTES);
    attn_kernel<<<dim3(SS / 64, BB * HH), 256, ATTN_SMEM_BYTES>>>(qp, kp, vp, cp);

    gemm_nt_kernel<0><<<ggrid, 256>>>(cp, wo, bo, out);      // out proj + bias
}

// round 3
// speedup vs baseline: 1.7491x; 1.7491x over previous
#include <cuda_runtime.h>
#include <cuda_bf16.h>
#include <math.h>
#include <stdint.h>

#define BB 4
#define SS 2048
#define DD 2048
#define HH 16
#define HD 128
#define MM (BB*SS)   // 8192

// ---------------- scratch (device globals: allocation-free rule) -----------
__device__ float g_q[(size_t)BB*HH*SS*HD];
__device__ float g_k[(size_t)BB*HH*SS*HD];
__device__ float g_v[(size_t)BB*HH*SS*HD];
__device__ __nv_bfloat16 g_xh[(size_t)MM*DD];
__device__ __nv_bfloat16 g_xl[(size_t)MM*DD];
__device__ __nv_bfloat16 g_wh[(size_t)4*DD*DD];
__device__ __nv_bfloat16 g_wl[(size_t)4*DD*DD];
__device__ __nv_bfloat16 g_ch[(size_t)MM*DD];
__device__ __nv_bfloat16 g_cl[(size_t)MM*DD];
__device__ float g_cos[SS*64];
__device__ float g_sin[SS*64];

// ---------------- helpers ----------------------------------------------------
__device__ __forceinline__ uint32_t smem_u32(const void* p) {
    uint32_t a;
    asm("{ .reg .u64 t; cvta.to.shared.u64 t, %1; cvt.u32.u64 %0, t; }"
        : "=r"(a) : "l"(p));
    return a;
}
__device__ __forceinline__ void cp16(uint32_t dst, const void* src) {
    asm volatile("cp.async.ca.shared.global [%0], [%1], 16;" :: "r"(dst), "l"(src));
}
#define CP_COMMIT() asm volatile("cp.async.commit_group;" ::: "memory")
#define CP_WAIT(n)  asm volatile("cp.async.wait_group %0;" :: "n"(n) : "memory")

__device__ __forceinline__ void mma16816(float* c, const uint32_t* a, const uint32_t* b) {
    asm volatile(
        "mma.sync.aligned.m16n8k16.row.col.f32.bf16.bf16.f32 "
        "{%0,%1,%2,%3}, {%4,%5,%6,%7}, {%8,%9}, {%0,%1,%2,%3};"
        : "+f"(c[0]), "+f"(c[1]), "+f"(c[2]), "+f"(c[3])
        : "r"(a[0]), "r"(a[1]), "r"(a[2]), "r"(a[3]), "r"(b[0]), "r"(b[1]));
}

// ---------------- RoPE table -------------------------------------------------
__global__ void rope_table_kernel() {
    int idx = blockIdx.x * blockDim.x + threadIdx.x;
    if (idx >= SS * 64) return;
    int s = idx >> 6, p = idx & 63;
    double invf = exp(-(double)p * (log(10000.0) / 64.0));
    float ang = (float)s * (float)invf;
    float sv, cv;
    sincosf(ang, &sv, &cv);
    g_cos[idx] = cv;
    g_sin[idx] = sv;
}

// ---------------- fp32 -> bf16 hi/lo split -----------------------------------
__global__ void cvt_split_kernel(const float* __restrict__ in,
                                 __nv_bfloat16* __restrict__ hi,
                                 __nv_bfloat16* __restrict__ lo, int n4) {
    int i = blockIdx.x * blockDim.x + threadIdx.x;
    if (i >= n4) return;
    float4 v = ((const float4*)in)[i];
    float a[4] = {v.x, v.y, v.z, v.w};
    __align__(8) __nv_bfloat16 h[4], l[4];
#pragma unroll
    for (int j = 0; j < 4; j++) {
        h[j] = __float2bfloat16(a[j]);
        l[j] = __float2bfloat16(a[j] - __bfloat162float(h[j]));
    }
    *(uint2*)&hi[(size_t)i * 4] = *(uint2*)h;
    *(uint2*)&lo[(size_t)i * 4] = *(uint2*)l;
}

// ---------------- HMMA GEMM: C = A @ W^T via bf16x3 --------------------------
// A: [M,2048] hi/lo bf16, W: [N,2048] hi/lo bf16.
// CTA tile 128x128, BK=64, 8 warps (2 x 4), warp tile 64x32.
// MODE 0: C[m,n] = acc + bias[n]        (plain [M,N])
// MODE 1: heads layout C[((b*H+h)*S+s)*HD + d]
// MODE 2: heads layout + RoPE
#define PITCH   36                      // words per 64-bf16 row (conflict-free)
#define TWORDS  (128*PITCH)             // 4608 words per tile
#define SWORDS  (4*TWORDS)              // 18432 words per stage (Ah,Al,Bh,Bl)
#define GEMM_SMEM (2*SWORDS*4)          // 147456 bytes
#define NSTG    (DD/64)                 // 32 k-stages

template<int MODE>
__global__ void __launch_bounds__(256, 1) gemm_mma_kernel(
    const __nv_bfloat16* __restrict__ Ah, const __nv_bfloat16* __restrict__ Al,
    const __nv_bfloat16* __restrict__ Bh, const __nv_bfloat16* __restrict__ Bl,
    const float* __restrict__ bias, float* __restrict__ C)
{
    extern __shared__ uint32_t sm4[];
    uint32_t sb = smem_u32(sm4);

    const int tid  = threadIdx.x;
    const int lane = tid & 31;
    const int wid  = tid >> 5;
    const int warpM = wid & 1;          // 0..1
    const int warpN = wid >> 1;         // 0..3
    const int g  = lane >> 2;
    const int t4 = lane & 3;

    const int row0 = blockIdx.y * 128;
    const int col0 = blockIdx.x * 128;

    const __nv_bfloat16* srcs[4] = {
        Ah + (size_t)row0 * DD, Al + (size_t)row0 * DD,
        Bh + (size_t)col0 * DD, Bl + (size_t)col0 * DD };

    // per-thread load slots: tile t, q = 0..3 -> f = tid + q*256
    const int lr = tid >> 3;            // row 0..31 base (f>>3 for q slices adds 32)
    const int lc = (tid & 7) * 8;       // bf16 col within 64
    const int lw = (tid & 7) * 4;       // word col

    float acc[4][4][4];
#pragma unroll
    for (int mi = 0; mi < 4; mi++)
#pragma unroll
        for (int ni = 0; ni < 4; ni++)
#pragma unroll
            for (int j = 0; j < 4; j++) acc[mi][ni][j] = 0.f;

    auto load_stage = [&](int kt, int buf) {
        const int k0 = kt * 64;
        uint32_t base = sb + (uint32_t)buf * SWORDS * 4;
#pragma unroll
        for (int t = 0; t < 4; t++) {
            const __nv_bfloat16* src = srcs[t] + k0;
            uint32_t dbase = base + (uint32_t)t * TWORDS * 4;
#pragma unroll
            for (int q = 0; q < 4; q++) {
                int r = lr + q * 32;
                cp16(dbase + (uint32_t)(r * PITCH + lw) * 4,
                     src + (size_t)r * DD + lc);
            }
        }
        CP_COMMIT();
    };

    load_stage(0, 0);

    for (int kt = 0; kt < NSTG; kt++) {
        int buf = kt & 1;
        if (kt + 1 < NSTG) {
            load_stage(kt + 1, buf ^ 1);
            CP_WAIT(1);
        } else {
            CP_WAIT(0);
        }
        __syncthreads();

        const uint32_t* st = sm4 + (size_t)buf * SWORDS;
        const uint32_t* tAh = st;
        const uint32_t* tAl = st + TWORDS;
        const uint32_t* tBh = st + 2 * TWORDS;
        const uint32_t* tBl = st + 3 * TWORDS;

#pragma unroll
        for (int ks = 0; ks < 4; ks++) {
            uint32_t ah[4][4], al[4][4], bh[4][2], bl[4][2];
#pragma unroll
            for (int mi = 0; mi < 4; mi++) {
                int rb = warpM * 64 + mi * 16 + g;
                int w0 = rb * PITCH + ks * 8 + t4;
                ah[mi][0] = tAh[w0];
                ah[mi][1] = tAh[w0 + 8 * PITCH];
                ah[mi][2] = tAh[w0 + 4];
                ah[mi][3] = tAh[w0 + 8 * PITCH + 4];
                al[mi][0] = tAl[w0];
                al[mi][1] = tAl[w0 + 8 * PITCH];
                al[mi][2] = tAl[w0 + 4];
                al[mi][3] = tAl[w0 + 8 * PITCH + 4];
            }
#pragma unroll
            for (int ni = 0; ni < 4; ni++) {
                int nb = warpN * 32 + ni * 8 + g;
                int w0 = nb * PITCH + ks * 8 + t4;
                bh[ni][0] = tBh[w0];
                bh[ni][1] = tBh[w0 + 4];
                bl[ni][0] = tBl[w0];
                bl[ni][1] = tBl[w0 + 4];
            }
#pragma unroll
            for (int mi = 0; mi < 4; mi++)
#pragma unroll
                for (int ni = 0; ni < 4; ni++) {
                    mma16816(acc[mi][ni], ah[mi], bh[ni]);
                    mma16816(acc[mi][ni], ah[mi], bl[ni]);
                    mma16816(acc[mi][ni], al[mi], bh[ni]);
                }
        }
        __syncthreads();
    }

    // ---------------- epilogue ----------------
#pragma unroll
    for (int mi = 0; mi < 4; mi++) {
#pragma unroll
        for (int ni = 0; ni < 4; ni++) {
            int m0 = row0 + warpM * 64 + mi * 16 + g;      // rows m0, m0+8
            int d  = warpN * 32 + ni * 8 + t4 * 2;          // local col (even)
            float v0 = acc[mi][ni][0], v1 = acc[mi][ni][1];
            float v2 = acc[mi][ni][2], v3 = acc[mi][ni][3];
            if (MODE == 0) {
                int n = col0 + d;
                float b0 = bias[n], b1 = bias[n + 1];
                *(float2*)&C[(size_t)m0 * DD + n]       = make_float2(v0 + b0, v1 + b1);
                *(float2*)&C[(size_t)(m0 + 8) * DD + n] = make_float2(v2 + b0, v3 + b1);
            } else {
                int h = blockIdx.x;
                int b0i = m0 >> 11, s0 = m0 & 2047;
                int b1i = (m0 + 8) >> 11, s1 = (m0 + 8) & 2047;
                if (MODE == 2) {
                    int p = d >> 1;
                    float c0 = g_cos[s0 * 64 + p], sn0 = g_sin[s0 * 64 + p];
                    float c1 = g_cos[s1 * 64 + p], sn1 = g_sin[s1 * 64 + p];
                    float r0 = v0 * c0 - v1 * sn0, r1 = v0 * sn0 + v1 * c0;
                    float r2 = v2 * c1 - v3 * sn1, r3 = v2 * sn1 + v3 * c1;
                    v0 = r0; v1 = r1; v2 = r2; v3 = r3;
                }
                *(float2*)&C[((size_t)(b0i * HH + h) * SS + s0) * HD + d] = make_float2(v0, v1);
                *(float2*)&C[((size_t)(b1i * HH + h) * SS + s1) * HD + d] = make_float2(v2, v3);
            }
        }
    }
}

// ---------------- flash attention (fp32 FFMA, known-good) --------------------
#define QPAD 132
#define KPAD 136
#define PPAD 132
#define ATTN_SMEM_FLOATS (64*QPAD + 128*KPAD + 128*128 + 64*PPAD)
#define ATTN_SMEM_BYTES  (ATTN_SMEM_FLOATS * 4)

__global__ void __launch_bounds__(256) attn_kernel(
    const float* __restrict__ Q, const float* __restrict__ K,
    const float* __restrict__ V,
    __nv_bfloat16* __restrict__ CH, __nv_bfloat16* __restrict__ CL)
{
    extern __shared__ float sm[];
    float* Qs  = sm;
    float* KsT = Qs + 64 * QPAD;
    float* Vs  = KsT + 128 * KPAD;
    float* Ps  = Vs + 128 * 128;

    int tid = threadIdx.x;
    int ty = tid >> 4, tx = tid & 15;
    int bh = blockIdx.y;
    int b = bh / HH, h = bh % HH;
    int q0 = blockIdx.x * 64;

    const float* Qb = Q + (size_t)bh * SS * HD;
    const float* Kb = K + (size_t)bh * SS * HD;
    const float* Vb = V + (size_t)bh * SS * HD;

#pragma unroll
    for (int l = 0; l < 8; l++) {
        int f = tid + l * 256;
        int r = f >> 5;
        int d = (f & 31) << 2;
        *(float4*)&Qs[r * QPAD + d] = *(const float4*)&Qb[(size_t)(q0 + r) * HD + d];
    }

    float mreg[4], lreg[4], o[4][8];
#pragma unroll
    for (int i = 0; i < 4; i++) {
        mreg[i] = -1e30f; lreg[i] = 0.f;
#pragma unroll
        for (int j = 0; j < 8; j++) o[i][j] = 0.f;
    }

    const float scale = 0.08838834764831845f;
    int nkt = q0 / 128 + 1;

    for (int kt = 0; kt < nkt; kt++) {
        int k0 = kt * 128;
        __syncthreads();
#pragma unroll
        for (int l = 0; l < 16; l++) {
            int f = tid + l * 256;
            int c = f & 127;
            int d = (f >> 7) << 2;
            float4 v = *(const float4*)&Kb[(size_t)(k0 + c) * HD + d];
            KsT[(d + 0) * KPAD + c] = v.x;
            KsT[(d + 1) * KPAD + c] = v.y;
            KsT[(d + 2) * KPAD + c] = v.z;
            KsT[(d + 3) * KPAD + c] = v.w;
        }
#pragma unroll
        for (int l = 0; l < 16; l++) {
            int f = tid + l * 256;
            int r = f >> 5;
            int d = (f & 31) << 2;
            *(float4*)&Vs[r * 128 + d] = *(const float4*)&Vb[(size_t)(k0 + r) * HD + d];
        }
        __syncthreads();

        float sv[4][8];
#pragma unroll
        for (int i = 0; i < 4; i++)
#pragma unroll
            for (int j = 0; j < 8; j++) sv[i][j] = 0.f;

#pragma unroll 2
        for (int d = 0; d < 128; d += 4) {
            float4 q4[4];
#pragma unroll
            for (int i = 0; i < 4; i++)
                q4[i] = *(const float4*)&Qs[(ty * 4 + i) * QPAD + d];
#pragma unroll
            for (int u = 0; u < 4; u++) {
                float4 ka = *(const float4*)&KsT[(d + u) * KPAD + tx * 8];
                float4 kb2 = *(const float4*)&KsT[(d + u) * KPAD + tx * 8 + 4];
                float kv[8] = {ka.x, ka.y, ka.z, ka.w, kb2.x, kb2.y, kb2.z, kb2.w};
#pragma unroll
                for (int i = 0; i < 4; i++) {
                    float qv = (u == 0) ? q4[i].x : (u == 1) ? q4[i].y
                             : (u == 2) ? q4[i].z : q4[i].w;
#pragma unroll
                    for (int j = 0; j < 8; j++)
                        sv[i][j] = fmaf(qv, kv[j], sv[i][j]);
                }
            }
        }

        bool last = (kt == nkt - 1);
#pragma unroll
        for (int i = 0; i < 4; i++) {
            int rg = q0 + ty * 4 + i;
            float rmax = -1e30f;
#pragma unroll
            for (int j = 0; j < 8; j++) {
                float xv = sv[i][j] * scale;
                if (last && (k0 + tx * 8 + j > rg)) xv = -1e30f;
                sv[i][j] = xv;
                rmax = fmaxf(rmax, xv);
            }
#pragma unroll
            for (int off = 8; off; off >>= 1)
                rmax = fmaxf(rmax, __shfl_xor_sync(0xffffffffu, rmax, off));
            float mnew = fmaxf(mreg[i], rmax);
            float al = __expf(mreg[i] - mnew);
            float rs = 0.f;
#pragma unroll
            for (int j = 0; j < 8; j++) {
                float p = __expf(sv[i][j] - mnew);
                sv[i][j] = p;
                rs += p;
            }
#pragma unroll
            for (int off = 8; off; off >>= 1)
                rs += __shfl_xor_sync(0xffffffffu, rs, off);
            lreg[i] = lreg[i] * al + rs;
            mreg[i] = mnew;
#pragma unroll
            for (int j = 0; j < 8; j++) o[i][j] *= al;
        }

#pragma unroll
        for (int i = 0; i < 4; i++) {
            float4 p0 = {sv[i][0], sv[i][1], sv[i][2], sv[i][3]};
            float4 p1 = {sv[i][4], sv[i][5], sv[i][6], sv[i][7]};
            *(float4*)&Ps[(ty * 4 + i) * PPAD + tx * 8] = p0;
            *(float4*)&Ps[(ty * 4 + i) * PPAD + tx * 8 + 4] = p1;
        }
        __syncthreads();

#pragma unroll 2
        for (int kk = 0; kk < 128; kk += 4) {
            float4 p4[4];
#pragma unroll
            for (int i = 0; i < 4; i++)
                p4[i] = *(const float4*)&Ps[(ty * 4 + i) * PPAD + kk];
#pragma unroll
            for (int u = 0; u < 4; u++) {
                float4 va = *(const float4*)&Vs[(kk + u) * 128 + tx * 8];
                float4 vb = *(const float4*)&Vs[(kk + u) * 128 + tx * 8 + 4];
                float vv[8] = {va.x, va.y, va.z, va.w, vb.x, vb.y, vb.z, vb.w};
#pragma unroll
                for (int i = 0; i < 4; i++) {
                    float pw = (u == 0) ? p4[i].x : (u == 1) ? p4[i].y
                             : (u == 2) ? p4[i].z : p4[i].w;
#pragma unroll
                    for (int j = 0; j < 8; j++)
                        o[i][j] = fmaf(pw, vv[j], o[i][j]);
                }
            }
        }
    }

#pragma unroll
    for (int i = 0; i < 4; i++) {
        float inv = 1.f / lreg[i];
        int r = q0 + ty * 4 + i;
        size_t idx = ((size_t)(b * SS + r) * DD + h * HD + tx * 8);
        __align__(16) __nv_bfloat16 hb[8], lb[8];
#pragma unroll
        for (int j = 0; j < 8; j++) {
            float f = o[i][j] * inv;
            __nv_bfloat16 hv = __float2bfloat16(f);
            hb[j] = hv;
            lb[j] = __float2bfloat16(f - __bfloat162float(hv));
        }
        *(uint4*)&CH[idx] = *(uint4*)hb;
        *(uint4*)&CL[idx] = *(uint4*)lb;
    }
}

// ---------------------------------------------------------------------------
extern "C" void kernel_launch(void* const* d_in, const int* in_sizes, int n_in,
                              void* d_out, int out_size)
{
    const float* x  = (const float*)d_in[0];
    const float* wq = (const float*)d_in[1];
    const float* wk = (const float*)d_in[2];
    const float* wv = (const float*)d_in[3];
    const float* wo = (const float*)d_in[4];
    const float* bo = (const float*)d_in[5];
    float* out = (float*)d_out;

    float *qp, *kp, *vp;
    __nv_bfloat16 *xh, *xl, *wh, *wl, *ch, *cl;
    cudaGetSymbolAddress((void**)&qp, g_q);
    cudaGetSymbolAddress((void**)&kp, g_k);
    cudaGetSymbolAddress((void**)&vp, g_v);
    cudaGetSymbolAddress((void**)&xh, g_xh);
    cudaGetSymbolAddress((void**)&xl, g_xl);
    cudaGetSymbolAddress((void**)&wh, g_wh);
    cudaGetSymbolAddress((void**)&wl, g_wl);
    cudaGetSymbolAddress((void**)&ch, g_ch);
    cudaGetSymbolAddress((void**)&cl, g_cl);

    rope_table_kernel<<<(SS * 64 + 255) / 256, 256>>>();

    {
        int n4 = MM * DD / 4;
        cvt_split_kernel<<<(n4 + 255) / 256, 256>>>(x, xh, xl, n4);
        int w4 = DD * DD / 4;
        cvt_split_kernel<<<(w4 + 255) / 256, 256>>>(wq, wh + (size_t)0 * DD * DD, wl + (size_t)0 * DD * DD, w4);
        cvt_split_kernel<<<(w4 + 255) / 256, 256>>>(wk, wh + (size_t)1 * DD * DD, wl + (size_t)1 * DD * DD, w4);
        cvt_split_kernel<<<(w4 + 255) / 256, 256>>>(wv, wh + (size_t)2 * DD * DD, wl + (size_t)2 * DD * DD, w4);
        cvt_split_kernel<<<(w4 + 255) / 256, 256>>>(wo, wh + (size_t)3 * DD * DD, wl + (size_t)3 * DD * DD, w4);
    }

    cudaFuncSetAttribute(gemm_mma_kernel<0>, cudaFuncAttributeMaxDynamicSharedMemorySize, GEMM_SMEM);
    cudaFuncSetAttribute(gemm_mma_kernel<1>, cudaFuncAttributeMaxDynamicSharedMemorySize, GEMM_SMEM);
    cudaFuncSetAttribute(gemm_mma_kernel<2>, cudaFuncAttributeMaxDynamicSharedMemorySize, GEMM_SMEM);

    dim3 ggrid(DD / 128, MM / 128);   // (16, 64)
    gemm_mma_kernel<2><<<ggrid, 256, GEMM_SMEM>>>(xh, xl, wh + (size_t)0 * DD * DD, wl + (size_t)0 * DD * DD, nullptr, qp);
    gemm_mma_kernel<2><<<ggrid, 256, GEMM_SMEM>>>(xh, xl, wh + (size_t)1 * DD * DD, wl + (size_t)1 * DD * DD, nullptr, kp);
    gemm_mma_kernel<1><<<ggrid, 256, GEMM_SMEM>>>(xh, xl, wh + (size_t)2 * DD * DD, wl + (size_t)2 * DD * DD, nullptr, vp);

    cudaFuncSetAttribute(attn_kernel, cudaFuncAttributeMaxDynamicSharedMemorySize, ATTN_SMEM_BYTES);
    attn_kernel<<<dim3(SS / 64, BB * HH), 256, ATTN_SMEM_BYTES>>>(qp, kp, vp, ch, cl);

    gemm_mma_kernel<0><<<ggrid, 256, GEMM_SMEM>>>(ch, cl, wh + (size_t)3 * DD * DD, wl + (size_t)3 * DD * DD, bo, out);
}

// round 5
// speedup vs baseline: 2.9423x; 1.6822x over previous
#include <cuda_runtime.h>
#include <cuda_bf16.h>
#include <math.h>
#include <stdint.h>

#define BB 4
#define SS 2048
#define DD 2048
#define HH 16
#define HD 128
#define MM (BB*SS)   // 8192

// ---------------- scratch (device globals: allocation-free rule) -----------
__device__ __nv_bfloat16 g_qh[(size_t)BB*HH*SS*HD];
__device__ __nv_bfloat16 g_ql[(size_t)BB*HH*SS*HD];
__device__ __nv_bfloat16 g_kh[(size_t)BB*HH*SS*HD];
__device__ __nv_bfloat16 g_kl[(size_t)BB*HH*SS*HD];
__device__ __nv_bfloat16 g_vh[(size_t)BB*HH*SS*HD];
__device__ __nv_bfloat16 g_vl[(size_t)BB*HH*SS*HD];
__device__ __nv_bfloat16 g_xh[(size_t)MM*DD];
__device__ __nv_bfloat16 g_xl[(size_t)MM*DD];
__device__ __nv_bfloat16 g_wh[(size_t)4*DD*DD];
__device__ __nv_bfloat16 g_wl[(size_t)4*DD*DD];
__device__ __nv_bfloat16 g_ch[(size_t)MM*DD];
__device__ __nv_bfloat16 g_cl[(size_t)MM*DD];
__device__ float g_cos[SS*64];
__device__ float g_sin[SS*64];

// ---------------- helpers ----------------------------------------------------
__device__ __forceinline__ uint32_t smem_u32(const void* p) {
    uint32_t a;
    asm("{ .reg .u64 t; cvta.to.shared.u64 t, %1; cvt.u32.u64 %0, t; }"
        : "=r"(a) : "l"(p));
    return a;
}
__device__ __forceinline__ void cp16(uint32_t dst, const void* src) {
    asm volatile("cp.async.cg.shared.global [%0], [%1], 16;" :: "r"(dst), "l"(src));
}
#define CP_COMMIT() asm volatile("cp.async.commit_group;" ::: "memory")
#define CP_WAIT(n)  asm volatile("cp.async.wait_group %0;" :: "n"(n) : "memory")

__device__ __forceinline__ void mma16816(float* c, const uint32_t* a, const uint32_t* b) {
    asm volatile(
        "mma.sync.aligned.m16n8k16.row.col.f32.bf16.bf16.f32 "
        "{%0,%1,%2,%3}, {%4,%5,%6,%7}, {%8,%9}, {%0,%1,%2,%3};"
        : "+f"(c[0]), "+f"(c[1]), "+f"(c[2]), "+f"(c[3])
        : "r"(a[0]), "r"(a[1]), "r"(a[2]), "r"(a[3]), "r"(b[0]), "r"(b[1]));
}
__device__ __forceinline__ void mma2(float* c, const uint32_t* a, uint32_t b0, uint32_t b1) {
    asm volatile(
        "mma.sync.aligned.m16n8k16.row.col.f32.bf16.bf16.f32 "
        "{%0,%1,%2,%3}, {%4,%5,%6,%7}, {%8,%9}, {%0,%1,%2,%3};"
        : "+f"(c[0]), "+f"(c[1]), "+f"(c[2]), "+f"(c[3])
        : "r"(a[0]), "r"(a[1]), "r"(a[2]), "r"(a[3]), "r"(b0), "r"(b1));
}
__device__ __forceinline__ void ldsm_x4(uint32_t* r, uint32_t addr) {
    asm volatile("ldmatrix.sync.aligned.m8n8.x4.shared.b16 {%0,%1,%2,%3}, [%4];"
        : "=r"(r[0]), "=r"(r[1]), "=r"(r[2]), "=r"(r[3]) : "r"(addr));
}
__device__ __forceinline__ void ldsm_x4_t(uint32_t* r, uint32_t addr) {
    asm volatile("ldmatrix.sync.aligned.m8n8.x4.trans.shared.b16 {%0,%1,%2,%3}, [%4];"
        : "=r"(r[0]), "=r"(r[1]), "=r"(r[2]), "=r"(r[3]) : "r"(addr));
}
// pack two f32 -> bf16x2 register: %1 -> high half, %2 -> low half
__device__ __forceinline__ uint32_t packbf(float lo, float hi) {
    uint32_t r;
    asm("cvt.rn.bf16x2.f32 %0, %1, %2;" : "=r"(r) : "f"(hi), "f"(lo));
    return r;
}
// hi/lo split of a pair (x -> low bf16 lane = k element 0)
__device__ __forceinline__ void split2(float x, float y, uint32_t& hp, uint32_t& lp) {
    hp = packbf(x, y);
    float hx = __int_as_float(hp << 16);
    float hy = __int_as_float(hp & 0xFFFF0000u);
    lp = packbf(x - hx, y - hy);
}
// fast exp on FMA/ALU pipes (x <= ~0), rel err ~2e-6
__device__ __forceinline__ float fexp(float x) {
    float y = fmaxf(x * 1.4426950408889634f, -120.f);
    float t = y + 12582912.f;
    int n = __float_as_int(t) - 0x4B400000;
    float f = y - (t - 12582912.f);
    float p = 1.3333558146e-3f;
    p = fmaf(p, f, 9.6181291076e-3f);
    p = fmaf(p, f, 5.5504108665e-2f);
    p = fmaf(p, f, 2.4022650696e-1f);
    p = fmaf(p, f, 6.9314718056e-1f);
    p = fmaf(p, f, 1.0f);
    return p * __int_as_float((127 + n) << 23);
}

// ---------------- RoPE table -------------------------------------------------
__global__ void rope_table_kernel() {
    int idx = blockIdx.x * blockDim.x + threadIdx.x;
    if (idx >= SS * 64) return;
    int s = idx >> 6, p = idx & 63;
    double invf = exp(-(double)p * (log(10000.0) / 64.0));
    float ang = (float)s * (float)invf;
    float sv, cv;
    sincosf(ang, &sv, &cv);
    g_cos[idx] = cv;
    g_sin[idx] = sv;
}

// ---------------- fp32 -> bf16 hi/lo split -----------------------------------
__global__ void cvt_split_kernel(const float* __restrict__ in,
                                 __nv_bfloat16* __restrict__ hi,
                                 __nv_bfloat16* __restrict__ lo, int n4) {
    int i = blockIdx.x * blockDim.x + threadIdx.x;
    if (i >= n4) return;
    float4 v = ((const float4*)in)[i];
    float a[4] = {v.x, v.y, v.z, v.w};
    __align__(8) __nv_bfloat16 h[4], l[4];
#pragma unroll
    for (int j = 0; j < 4; j++) {
        h[j] = __float2bfloat16(a[j]);
        l[j] = __float2bfloat16(a[j] - __bfloat162float(h[j]));
    }
    *(uint2*)&hi[(size_t)i * 4] = *(uint2*)h;
    *(uint2*)&lo[(size_t)i * 4] = *(uint2*)l;
}

// ---------------- HMMA GEMM: C = A @ W^T via bf16x3 --------------------------
// MODE 0: f32 C[m,n] = acc + bias[n]
// MODE 1: bf16 hi/lo planes, heads layout
// MODE 2: bf16 hi/lo planes, heads layout + RoPE
#define PITCH   36
#define TWORDS  (128*PITCH)
#define SWORDS  (4*TWORDS)
#define GEMM_SMEM (2*SWORDS*4)
#define NSTG    (DD/64)

template<int MODE>
__global__ void __launch_bounds__(256, 1) gemm_mma_kernel(
    const __nv_bfloat16* __restrict__ Ah, const __nv_bfloat16* __restrict__ Al,
    const __nv_bfloat16* __restrict__ Bh, const __nv_bfloat16* __restrict__ Bl,
    const float* __restrict__ bias, float* __restrict__ C,
    __nv_bfloat16* __restrict__ Ch, __nv_bfloat16* __restrict__ Cl)
{
    extern __shared__ uint32_t sm4[];
    uint32_t sb = smem_u32(sm4);

    const int tid  = threadIdx.x;
    const int lane = tid & 31;
    const int wid  = tid >> 5;
    const int warpM = wid & 1;
    const int warpN = wid >> 1;
    const int g  = lane >> 2;
    const int t4 = lane & 3;
    // ldsm lane maps
    const int l16 = lane & 15, lh2 = lane >> 4;
    const int bkey = (lane & 7) | ((lane >> 4) << 3);
    const int bch  = (lane >> 3) & 1;

    const int row0 = blockIdx.y * 128;
    const int col0 = blockIdx.x * 128;

    const __nv_bfloat16* srcs[4] = {
        Ah + (size_t)row0 * DD, Al + (size_t)row0 * DD,
        Bh + (size_t)col0 * DD, Bl + (size_t)col0 * DD };

    const int lr = tid >> 3;
    const int lc = (tid & 7) * 8;
    const int lw = (tid & 7) * 4;

    float acc[4][4][4];
#pragma unroll
    for (int mi = 0; mi < 4; mi++)
#pragma unroll
        for (int ni = 0; ni < 4; ni++)
#pragma unroll
            for (int j = 0; j < 4; j++) acc[mi][ni][j] = 0.f;

    auto load_stage = [&](int kt, int buf) {
        const int k0 = kt * 64;
        uint32_t base = sb + (uint32_t)buf * SWORDS * 4;
#pragma unroll
        for (int t = 0; t < 4; t++) {
            const __nv_bfloat16* src = srcs[t] + k0;
            uint32_t dbase = base + (uint32_t)t * TWORDS * 4;
#pragma unroll
            for (int q = 0; q < 4; q++) {
                int r = lr + q * 32;
                cp16(dbase + (uint32_t)(r * PITCH + lw) * 4,
                     src + (size_t)r * DD + lc);
            }
        }
        CP_COMMIT();
    };

    load_stage(0, 0);

    const int awoff = (warpM * 64 + l16) * PITCH;
    const int bwoff = (warpN * 32 + bkey) * PITCH + bch * 4;

    for (int kt = 0; kt < NSTG; kt++) {
        int buf = kt & 1;
        if (kt + 1 < NSTG) {
            load_stage(kt + 1, buf ^ 1);
            CP_WAIT(1);
        } else {
            CP_WAIT(0);
        }
        __syncthreads();

        uint32_t tb = sb + (uint32_t)buf * SWORDS * 4;
        uint32_t pAh = tb;
        uint32_t pAl = tb + TWORDS * 4;
        uint32_t pBh = tb + 2 * TWORDS * 4;
        uint32_t pBl = tb + 3 * TWORDS * 4;

#pragma unroll
        for (int ks = 0; ks < 4; ks++) {
            uint32_t ah[4][4], al[4][4], bh[4][2], bl[4][2];
#pragma unroll
            for (int mi = 0; mi < 4; mi++) {
                uint32_t wo = (uint32_t)(awoff + mi * 16 * PITCH + ks * 8 + lh2 * 4) * 4;
                ldsm_x4(ah[mi], pAh + wo);
                ldsm_x4(al[mi], pAl + wo);
            }
#pragma unroll
            for (int jj = 0; jj < 2; jj++) {
                uint32_t wo = (uint32_t)(bwoff + jj * 16 * PITCH + ks * 8) * 4;
                uint32_t r[4];
                ldsm_x4(r, pBh + wo);
                bh[2*jj][0] = r[0]; bh[2*jj][1] = r[1];
                bh[2*jj+1][0] = r[2]; bh[2*jj+1][1] = r[3];
                ldsm_x4(r, pBl + wo);
                bl[2*jj][0] = r[0]; bl[2*jj][1] = r[1];
                bl[2*jj+1][0] = r[2]; bl[2*jj+1][1] = r[3];
            }
#pragma unroll
            for (int mi = 0; mi < 4; mi++)
#pragma unroll
                for (int ni = 0; ni < 4; ni++) {
                    mma16816(acc[mi][ni], ah[mi], bh[ni]);
                    mma16816(acc[mi][ni], ah[mi], bl[ni]);
                    mma16816(acc[mi][ni], al[mi], bh[ni]);
                }
        }
        __syncthreads();
    }

    // ---------------- epilogue ----------------
#pragma unroll
    for (int mi = 0; mi < 4; mi++) {
#pragma unroll
        for (int ni = 0; ni < 4; ni++) {
            int m0 = row0 + warpM * 64 + mi * 16 + g;
            int d  = warpN * 32 + ni * 8 + t4 * 2;
            float v0 = acc[mi][ni][0], v1 = acc[mi][ni][1];
            float v2 = acc[mi][ni][2], v3 = acc[mi][ni][3];
            if (MODE == 0) {
                int n = col0 + d;
                float b0 = bias[n], b1 = bias[n + 1];
                *(float2*)&C[(size_t)m0 * DD + n]       = make_float2(v0 + b0, v1 + b1);
                *(float2*)&C[(size_t)(m0 + 8) * DD + n] = make_float2(v2 + b0, v3 + b1);
            } else {
                int h = blockIdx.x;
                int b0i = m0 >> 11, s0 = m0 & 2047;
                int b1i = (m0 + 8) >> 11, s1 = (m0 + 8) & 2047;
                if (MODE == 2) {
                    int p = d >> 1;
                    float c0 = g_cos[s0 * 64 + p], sn0 = g_sin[s0 * 64 + p];
                    float c1 = g_cos[s1 * 64 + p], sn1 = g_sin[s1 * 64 + p];
                    float r0 = v0 * c0 - v1 * sn0, r1 = v0 * sn0 + v1 * c0;
                    float r2 = v2 * c1 - v3 * sn1, r3 = v2 * sn1 + v3 * c1;
                    v0 = r0; v1 = r1; v2 = r2; v3 = r3;
                }
                size_t i0 = ((size_t)(b0i * HH + h) * SS + s0) * HD + d;
                size_t i1 = ((size_t)(b1i * HH + h) * SS + s1) * HD + d;
                uint32_t hp, lp;
                split2(v0, v1, hp, lp);
                *(uint32_t*)&Ch[i0] = hp;
                *(uint32_t*)&Cl[i0] = lp;
                split2(v2, v3, hp, lp);
                *(uint32_t*)&Ch[i1] = hp;
                *(uint32_t*)&Cl[i1] = lp;
            }
        }
    }
}

// ---------------- HMMA flash attention ---------------------------------------
// BM=128 (8 warps x 16 rows), BN=64 keys/tile, HD=128, bf16x3 emulation.
#define AT_QH 0
#define AT_QL 9216
#define AT_KV 18432
#define AT_STG 18432
#define ATT_SMEM (55296*4)   // 221184 B

__global__ void __launch_bounds__(256, 1) attn_mma_kernel(
    const __nv_bfloat16* __restrict__ Qh, const __nv_bfloat16* __restrict__ Ql,
    const __nv_bfloat16* __restrict__ Kh, const __nv_bfloat16* __restrict__ Kl,
    const __nv_bfloat16* __restrict__ Vh, const __nv_bfloat16* __restrict__ Vl,
    __nv_bfloat16* __restrict__ CH, __nv_bfloat16* __restrict__ CL)
{
    extern __shared__ uint32_t smw[];
    uint32_t sb = smem_u32(smw);
    const int tid = threadIdx.x, lane = tid & 31, w = tid >> 5;
    const int g = lane >> 2, t4 = lane & 3;
    const int bh = blockIdx.y;
    const int bidx = bh / HH, hidx = bh % HH;
    const int qb = gridDim.x - 1 - blockIdx.x;   // big tiles first
    const int q0 = qb * 128;
    const int nkt = qb * 2 + 2;
    const size_t hb = (size_t)bh * SS * HD;

    // ldsm lane maps
    const int l16 = lane & 15, lh2 = lane >> 4;
    const int bkey = (lane & 7) | ((lane >> 4) << 3);
    const int bch  = (lane >> 3) & 1;
    const int vkey = (lane & 7) | (((lane >> 3) & 1) << 3);
    const int vch  = lane >> 4;

    // ---- load Q (hi/lo planes): 2 planes x 128 rows x 16 chunks of 16B ----
    {
        const __nv_bfloat16* qs0 = Qh + hb + (size_t)q0 * HD;
        const __nv_bfloat16* qs1 = Ql + hb + (size_t)q0 * HD;
#pragma unroll
        for (int i = 0; i < 16; i++) {
            int idx = tid + i * 256;            // 0..4095
            int pl = idx >> 11;                  // plane 0/1
            int c = idx & 2047;
            int row = c >> 4;                    // 0..127
            int piece = c & 15;                  // 0..15 (16B chunks)
            uint32_t dw = (pl ? AT_QL : AT_QH) + (piece >> 3) * 4608
                        + row * 36 + (piece & 7) * 4;
            cp16(sb + dw * 4, (pl ? qs1 : qs0) + (size_t)row * HD + piece * 8);
        }
    }
    const __nv_bfloat16* kvsrc[4] = {Kh + hb, Kl + hb, Vh + hb, Vl + hb};
    auto load_kv = [&](int kt, int buf) {
        int k0 = kt * 64;
#pragma unroll
        for (int i = 0; i < 16; i++) {
            int idx = tid + i * 256;            // 0..4095
            int pl = idx >> 10;                  // plane 0..3 (Kh,Kl,Vh,Vl)
            int c = idx & 1023;
            int row = c >> 4;                    // 0..63
            int piece = c & 15;                  // 0..15
            uint32_t dw = AT_KV + buf * AT_STG + pl * 4608 + (piece >> 3) * 2304
                        + row * 36 + (piece & 7) * 4;
            cp16(sb + dw * 4, kvsrc[pl] + (size_t)(k0 + row) * HD + piece * 8);
        }
    };
    load_kv(0, 0); CP_COMMIT();
    load_kv(1, 1); CP_COMMIT();

    float ofr[16][4];
#pragma unroll
    for (int i = 0; i < 16; i++)
#pragma unroll
        for (int j = 0; j < 4; j++) ofr[i][j] = 0.f;
    float m0 = -1e30f, m1 = -1e30f, l0 = 0.f, l1 = 0.f;
    const float scale = 0.08838834764831845f;

    const uint32_t qwoff = (uint32_t)(w * 16 + l16) * 36;
    const int rowg = q0 + w * 16 + g;

    for (int kt = 0; kt < nkt; kt++) {
        if (kt + 1 < nkt) { CP_WAIT(1); } else { CP_WAIT(0); }
        __syncthreads();
        int buf = kt & 1;
        uint32_t stg = AT_KV + (uint32_t)buf * AT_STG;
        bool active = !(kt == nkt - 1 && w < 4);

        if (active) {
            // ---- S = Q K^T (bf16x3) ----
            float sf[8][4];
#pragma unroll
            for (int n = 0; n < 8; n++)
#pragma unroll
                for (int c = 0; c < 4; c++) sf[n][c] = 0.f;

#pragma unroll
            for (int ks = 0; ks < 8; ks++) {
                uint32_t qwo = ((uint32_t)(ks >> 2) * 4608 + qwoff + (ks & 3) * 8 + lh2 * 4) * 4;
                uint32_t qh4[4], ql4[4];
                ldsm_x4(qh4, sb + AT_QH * 4 + qwo);
                ldsm_x4(ql4, sb + AT_QL * 4 + qwo);
                uint32_t khf[8][2], klf[8][2];
#pragma unroll
                for (int j = 0; j < 4; j++) {
                    uint32_t kwo = (stg + (uint32_t)(ks >> 2) * 2304
                                  + (uint32_t)(j * 16 + bkey) * 36 + (ks & 3) * 8 + bch * 4) * 4;
                    uint32_t r[4];
                    ldsm_x4(r, sb + kwo);            // Kh plane
                    khf[2*j][0] = r[0]; khf[2*j][1] = r[1];
                    khf[2*j+1][0] = r[2]; khf[2*j+1][1] = r[3];
                    ldsm_x4(r, sb + kwo + 4608 * 4); // Kl plane
                    klf[2*j][0] = r[0]; klf[2*j][1] = r[1];
                    klf[2*j+1][0] = r[2]; klf[2*j+1][1] = r[3];
                }
#pragma unroll
                for (int n = 0; n < 8; n++) {
                    mma16816(sf[n], qh4, khf[n]);
                    mma16816(sf[n], qh4, klf[n]);
                    mma16816(sf[n], ql4, khf[n]);
                }
            }

            // ---- online softmax ----
            int k0 = kt * 64;
            bool domask = (kt >= nkt - 2);
            float mx0 = -1e30f, mx1 = -1e30f;
#pragma unroll
            for (int n = 0; n < 8; n++) {
#pragma unroll
                for (int c = 0; c < 4; c++) {
                    float v = sf[n][c] * scale;
                    if (domask) {
                        int col = k0 + n * 8 + 2 * t4 + (c & 1);
                        int row = rowg + ((c >> 1) << 3);
                        if (col > row) v = -1e30f;
                    }
                    sf[n][c] = v;
                    if (c < 2) mx0 = fmaxf(mx0, v); else mx1 = fmaxf(mx1, v);
                }
            }
            mx0 = fmaxf(mx0, __shfl_xor_sync(0xffffffffu, mx0, 1));
            mx0 = fmaxf(mx0, __shfl_xor_sync(0xffffffffu, mx0, 2));
            mx1 = fmaxf(mx1, __shfl_xor_sync(0xffffffffu, mx1, 1));
            mx1 = fmaxf(mx1, __shfl_xor_sync(0xffffffffu, mx1, 2));
            float mn0 = fmaxf(m0, mx0), mn1 = fmaxf(m1, mx1);
            float a0 = fexp(m0 - mn0), a1 = fexp(m1 - mn1);
            m0 = mn0; m1 = mn1;
            float s0 = 0.f, s1 = 0.f;
#pragma unroll
            for (int n = 0; n < 8; n++) {
                sf[n][0] = fexp(sf[n][0] - mn0); s0 += sf[n][0];
                sf[n][1] = fexp(sf[n][1] - mn0); s0 += sf[n][1];
                sf[n][2] = fexp(sf[n][2] - mn1); s1 += sf[n][2];
                sf[n][3] = fexp(sf[n][3] - mn1); s1 += sf[n][3];
            }
            s0 += __shfl_xor_sync(0xffffffffu, s0, 1);
            s0 += __shfl_xor_sync(0xffffffffu, s0, 2);
            s1 += __shfl_xor_sync(0xffffffffu, s1, 1);
            s1 += __shfl_xor_sync(0xffffffffu, s1, 2);
            l0 = l0 * a0 + s0;
            l1 = l1 * a1 + s1;
#pragma unroll
            for (int nc = 0; nc < 16; nc++) {
                ofr[nc][0] *= a0; ofr[nc][1] *= a0;
                ofr[nc][2] *= a1; ofr[nc][3] *= a1;
            }

            // ---- P frags (hi/lo) from sf, register-only ----
            uint32_t ph[4][4], plo[4][4];
#pragma unroll
            for (int kb = 0; kb < 4; kb++) {
                split2(sf[2*kb][0],   sf[2*kb][1],   ph[kb][0], plo[kb][0]);
                split2(sf[2*kb][2],   sf[2*kb][3],   ph[kb][1], plo[kb][1]);
                split2(sf[2*kb+1][0], sf[2*kb+1][1], ph[kb][2], plo[kb][2]);
                split2(sf[2*kb+1][2], sf[2*kb+1][3], ph[kb][3], plo[kb][3]);
            }

            // ---- O += P V (bf16x3) ----
#pragma unroll
            for (int kb = 0; kb < 4; kb++) {
                uint32_t krow = (uint32_t)(kb * 16 + vkey) * 36;
#pragma unroll
                for (int jj = 0; jj < 8; jj++) {
                    int cj = jj * 2 + vch;
                    uint32_t vwo = (stg + 9216u + (uint32_t)(cj >> 3) * 2304
                                  + krow + (uint32_t)(cj & 7) * 4) * 4;
                    uint32_t rv[4], rl[4];
                    ldsm_x4_t(rv, sb + vwo);             // Vh
                    ldsm_x4_t(rl, sb + vwo + 4608 * 4);  // Vl
                    mma2(ofr[2*jj],   ph[kb], rv[0], rv[1]);
                    mma2(ofr[2*jj],   ph[kb], rl[0], rl[1]);
                    mma2(ofr[2*jj],   plo[kb], rv[0], rv[1]);
                    mma2(ofr[2*jj+1], ph[kb], rv[2], rv[3]);
                    mma2(ofr[2*jj+1], ph[kb], rl[2], rl[3]);
                    mma2(ofr[2*jj+1], plo[kb], rv[2], rv[3]);
                }
            }
        }
        __syncthreads();
        if (kt + 2 < nkt) { load_kv(kt + 2, buf); CP_COMMIT(); }
    }

    // ---- epilogue: normalize + write bf16 hi/lo ctx ----
    float i0 = 1.f / l0, i1 = 1.f / l1;
    int r0 = q0 + w * 16 + g, r1 = r0 + 8;
    size_t base0 = ((size_t)(bidx * SS + r0)) * DD + hidx * HD;
    size_t base1 = ((size_t)(bidx * SS + r1)) * DD + hidx * HD;
#pragma unroll
    for (int nc = 0; nc < 16; nc++) {
        int d = nc * 8 + 2 * t4;
        uint32_t hp, lp;
        split2(ofr[nc][0] * i0, ofr[nc][1] * i0, hp, lp);
        *(uint32_t*)&CH[base0 + d] = hp;
        *(uint32_t*)&CL[base0 + d] = lp;
        split2(ofr[nc][2] * i1, ofr[nc][3] * i1, hp, lp);
        *(uint32_t*)&CH[base1 + d] = hp;
        *(uint32_t*)&CL[base1 + d] = lp;
    }
}

// ---------------------------------------------------------------------------
extern "C" void kernel_launch(void* const* d_in, const int* in_sizes, int n_in,
                              void* d_out, int out_size)
{
    const float* x  = (const float*)d_in[0];
    const float* wq = (const float*)d_in[1];
    const float* wk = (const float*)d_in[2];
    const float* wv = (const float*)d_in[3];
    const float* wo = (const float*)d_in[4];
    const float* bo = (const float*)d_in[5];
    float* out = (float*)d_out;

    __nv_bfloat16 *qh, *ql, *kh, *kl, *vh, *vl, *xh, *xl, *wh, *wl, *ch, *cl;
    cudaGetSymbolAddress((void**)&qh, g_qh);
    cudaGetSymbolAddress((void**)&ql, g_ql);
    cudaGetSymbolAddress((void**)&kh, g_kh);
    cudaGetSymbolAddress((void**)&kl, g_kl);
    cudaGetSymbolAddress((void**)&vh, g_vh);
    cudaGetSymbolAddress((void**)&vl, g_vl);
    cudaGetSymbolAddress((void**)&xh, g_xh);
    cudaGetSymbolAddress((void**)&xl, g_xl);
    cudaGetSymbolAddress((void**)&wh, g_wh);
    cudaGetSymbolAddress((void**)&wl, g_wl);
    cudaGetSymbolAddress((void**)&ch, g_ch);
    cudaGetSymbolAddress((void**)&cl, g_cl);

    rope_table_kernel<<<(SS * 64 + 255) / 256, 256>>>();

    {
        int n4 = MM * DD / 4;
        cvt_split_kernel<<<(n4 + 255) / 256, 256>>>(x, xh, xl, n4);
        int w4 = DD * DD / 4;
        cvt_split_kernel<<<(w4 + 255) / 256, 256>>>(wq, wh + (size_t)0 * DD * DD, wl + (size_t)0 * DD * DD, w4);
        cvt_split_kernel<<<(w4 + 255) / 256, 256>>>(wk, wh + (size_t)1 * DD * DD, wl + (size_t)1 * DD * DD, w4);
        cvt_split_kernel<<<(w4 + 255) / 256, 256>>>(wv, wh + (size_t)2 * DD * DD, wl + (size_t)2 * DD * DD, w4);
        cvt_split_kernel<<<(w4 + 255) / 256, 256>>>(wo, wh + (size_t)3 * DD * DD, wl + (size_t)3 * DD * DD, w4);
    }

    cudaFuncSetAttribute(gemm_mma_kernel<0>, cudaFuncAttributeMaxDynamicSharedMemorySize, GEMM_SMEM);
    cudaFuncSetAttribute(gemm_mma_kernel<1>, cudaFuncAttributeMaxDynamicSharedMemorySize, GEMM_SMEM);
    cudaFuncSetAttribute(gemm_mma_kernel<2>, cudaFuncAttributeMaxDynamicSharedMemorySize, GEMM_SMEM);
    cudaFuncSetAttribute(attn_mma_kernel, cudaFuncAttributeMaxDynamicSharedMemorySize, ATT_SMEM);

    dim3 ggrid(DD / 128, MM / 128);   // (16, 64)
    gemm_mma_kernel<2><<<ggrid, 256, GEMM_SMEM>>>(xh, xl, wh + (size_t)0 * DD * DD, wl + (size_t)0 * DD * DD, nullptr, nullptr, qh, ql);
    gemm_mma_kernel<2><<<ggrid, 256, GEMM_SMEM>>>(xh, xl, wh + (size_t)1 * DD * DD, wl + (size_t)1 * DD * DD, nullptr, nullptr, kh, kl);
    gemm_mma_kernel<1><<<ggrid, 256, GEMM_SMEM>>>(xh, xl, wh + (size_t)2 * DD * DD, wl + (size_t)2 * DD * DD, nullptr, nullptr, vh, vl);

    attn_mma_kernel<<<dim3(SS / 128, BB * HH), 256, ATT_SMEM>>>(qh, ql, kh, kl, vh, vl, ch, cl);

    gemm_mma_kernel<0><<<ggrid, 256, GEMM_SMEM>>>(ch, cl, wh + (size_t)3 * DD * DD, wl + (size_t)3 * DD * DD, bo, out, nullptr, nullptr);
}

// round 6
// speedup vs baseline: 2.9912x; 1.0166x over previous
#include <cuda_runtime.h>
#include <cuda_bf16.h>
#include <math.h>
#include <stdint.h>

#define BB 4
#define SS 2048
#define DD 2048
#define HH 16
#define HD 128
#define MM (BB*SS)   // 8192

// ---------------- scratch (device globals: allocation-free rule) -----------
__device__ __nv_bfloat16 g_qh[(size_t)BB*HH*SS*HD];
__device__ __nv_bfloat16 g_ql[(size_t)BB*HH*SS*HD];
__device__ __nv_bfloat16 g_kh[(size_t)BB*HH*SS*HD];
__device__ __nv_bfloat16 g_kl[(size_t)BB*HH*SS*HD];
__device__ __nv_bfloat16 g_vh[(size_t)BB*HH*SS*HD];
__device__ __nv_bfloat16 g_vl[(size_t)BB*HH*SS*HD];
__device__ __nv_bfloat16 g_xh[(size_t)MM*DD];
__device__ __nv_bfloat16 g_xl[(size_t)MM*DD];
__device__ __nv_bfloat16 g_wh[(size_t)4*DD*DD];
__device__ __nv_bfloat16 g_wl[(size_t)4*DD*DD];
__device__ __nv_bfloat16 g_ch[(size_t)MM*DD];
__device__ __nv_bfloat16 g_cl[(size_t)MM*DD];
__device__ float g_cos[SS*64];
__device__ float g_sin[SS*64];

// ---------------- helpers ----------------------------------------------------
__device__ __forceinline__ uint32_t smem_u32(const void* p) {
    uint32_t a;
    asm("{ .reg .u64 t; cvta.to.shared.u64 t, %1; cvt.u32.u64 %0, t; }"
        : "=r"(a) : "l"(p));
    return a;
}
__device__ __forceinline__ void cp16(uint32_t dst, const void* src) {
    asm volatile("cp.async.cg.shared.global [%0], [%1], 16;" :: "r"(dst), "l"(src));
}
#define CP_COMMIT() asm volatile("cp.async.commit_group;" ::: "memory")
#define CP_WAIT(n)  asm volatile("cp.async.wait_group %0;" :: "n"(n) : "memory")

__device__ __forceinline__ void mma16816(float* c, const uint32_t* a, const uint32_t* b) {
    asm volatile(
        "mma.sync.aligned.m16n8k16.row.col.f32.bf16.bf16.f32 "
        "{%0,%1,%2,%3}, {%4,%5,%6,%7}, {%8,%9}, {%0,%1,%2,%3};"
        : "+f"(c[0]), "+f"(c[1]), "+f"(c[2]), "+f"(c[3])
        : "r"(a[0]), "r"(a[1]), "r"(a[2]), "r"(a[3]), "r"(b[0]), "r"(b[1]));
}
__device__ __forceinline__ void mma2(float* c, const uint32_t* a, uint32_t b0, uint32_t b1) {
    asm volatile(
        "mma.sync.aligned.m16n8k16.row.col.f32.bf16.bf16.f32 "
        "{%0,%1,%2,%3}, {%4,%5,%6,%7}, {%8,%9}, {%0,%1,%2,%3};"
        : "+f"(c[0]), "+f"(c[1]), "+f"(c[2]), "+f"(c[3])
        : "r"(a[0]), "r"(a[1]), "r"(a[2]), "r"(a[3]), "r"(b0), "r"(b1));
}
__device__ __forceinline__ void ldsm_x4(uint32_t* r, uint32_t addr) {
    asm volatile("ldmatrix.sync.aligned.m8n8.x4.shared.b16 {%0,%1,%2,%3}, [%4];"
        : "=r"(r[0]), "=r"(r[1]), "=r"(r[2]), "=r"(r[3]) : "r"(addr));
}
__device__ __forceinline__ void ldsm_x4_t(uint32_t* r, uint32_t addr) {
    asm volatile("ldmatrix.sync.aligned.m8n8.x4.trans.shared.b16 {%0,%1,%2,%3}, [%4];"
        : "=r"(r[0]), "=r"(r[1]), "=r"(r[2]), "=r"(r[3]) : "r"(addr));
}
__device__ __forceinline__ uint32_t packbf(float lo, float hi) {
    uint32_t r;
    asm("cvt.rn.bf16x2.f32 %0, %1, %2;" : "=r"(r) : "f"(hi), "f"(lo));
    return r;
}
__device__ __forceinline__ void split2(float x, float y, uint32_t& hp, uint32_t& lp) {
    hp = packbf(x, y);
    float hx = __int_as_float(hp << 16);
    float hy = __int_as_float(hp & 0xFFFF0000u);
    lp = packbf(x - hx, y - hy);
}
// fast exp on FMA/ALU pipes (x <= ~0), rel err ~2e-6
__device__ __forceinline__ float fexp(float x) {
    float y = fmaxf(x * 1.4426950408889634f, -120.f);
    float t = y + 12582912.f;
    int n = __float_as_int(t) - 0x4B400000;
    float f = y - (t - 12582912.f);
    float p = 1.3333558146e-3f;
    p = fmaf(p, f, 9.6181291076e-3f);
    p = fmaf(p, f, 5.5504108665e-2f);
    p = fmaf(p, f, 2.4022650696e-1f);
    p = fmaf(p, f, 6.9314718056e-1f);
    p = fmaf(p, f, 1.0f);
    return p * __int_as_float((127 + n) << 23);
}

// ---------------- RoPE table -------------------------------------------------
__global__ void rope_table_kernel() {
    int idx = blockIdx.x * blockDim.x + threadIdx.x;
    if (idx >= SS * 64) return;
    int s = idx >> 6, p = idx & 63;
    double invf = exp(-(double)p * (log(10000.0) / 64.0));
    float ang = (float)s * (float)invf;
    float sv, cv;
    sincosf(ang, &sv, &cv);
    g_cos[idx] = cv;
    g_sin[idx] = sv;
}

// ---------------- fp32 -> bf16 hi/lo split -----------------------------------
__global__ void cvt_split_kernel(const float* __restrict__ in,
                                 __nv_bfloat16* __restrict__ hi,
                                 __nv_bfloat16* __restrict__ lo, int n4) {
    int i = blockIdx.x * blockDim.x + threadIdx.x;
    if (i >= n4) return;
    float4 v = ((const float4*)in)[i];
    float a[4] = {v.x, v.y, v.z, v.w};
    __align__(8) __nv_bfloat16 h[4], l[4];
#pragma unroll
    for (int j = 0; j < 4; j++) {
        h[j] = __float2bfloat16(a[j]);
        l[j] = __float2bfloat16(a[j] - __bfloat162float(h[j]));
    }
    *(uint2*)&hi[(size_t)i * 4] = *(uint2*)h;
    *(uint2*)&lo[(size_t)i * 4] = *(uint2*)l;
}

// two tensors in one launch (keeps launch count aligned for ncu targeting)
__global__ void cvt_split2_kernel(const float* __restrict__ in0, const float* __restrict__ in1,
                                  __nv_bfloat16* __restrict__ h0, __nv_bfloat16* __restrict__ l0,
                                  __nv_bfloat16* __restrict__ h1, __nv_bfloat16* __restrict__ l1,
                                  int n4) {
    int i = blockIdx.x * blockDim.x + threadIdx.x;
    if (i >= 2 * n4) return;
    int which = (i >= n4);
    int j = which ? i - n4 : i;
    const float* in = which ? in1 : in0;
    __nv_bfloat16* hi = which ? h1 : h0;
    __nv_bfloat16* lo = which ? l1 : l0;
    float4 v = ((const float4*)in)[j];
    float a[4] = {v.x, v.y, v.z, v.w};
    __align__(8) __nv_bfloat16 h[4], l[4];
#pragma unroll
    for (int k = 0; k < 4; k++) {
        h[k] = __float2bfloat16(a[k]);
        l[k] = __float2bfloat16(a[k] - __bfloat162float(h[k]));
    }
    *(uint2*)&hi[(size_t)j * 4] = *(uint2*)h;
    *(uint2*)&lo[(size_t)j * 4] = *(uint2*)l;
}

// ---------------- shared GEMM mainloop (bf16x3, 128x128 tile, KSTG=32) -------
// pitch 20 words per 32-bf16 row: ldmatrix phases conflict-free
#define PITCH   20
#define KSTG    32
#define TWORDS  (128*PITCH)          // 2560
#define SWORDS  (4*TWORDS)           // 10240
#define GEMM_SMEM (2*SWORDS*4)       // 81920 bytes -> 2 CTAs/SM
#define NSTG    (DD/KSTG)            // 64

__device__ __forceinline__ void gemm_core(
    const __nv_bfloat16* __restrict__ src0, const __nv_bfloat16* __restrict__ src1,
    const __nv_bfloat16* __restrict__ src2, const __nv_bfloat16* __restrict__ src3,
    uint32_t sb, float (&acc)[4][4][4])
{
    const int tid  = threadIdx.x;
    const int lane = tid & 31;
    const int wid  = tid >> 5;
    const int warpM = wid & 1;
    const int warpN = wid >> 1;
    const int l16 = lane & 15, lh2 = lane >> 4;
    const int bkey = (lane & 7) | ((lane >> 4) << 3);
    const int bch  = (lane >> 3) & 1;

    const __nv_bfloat16* srcs[4] = {src0, src1, src2, src3};
    const int r_ld = tid >> 2;       // 0..63 (q adds 64)
    const int c_ld = tid & 3;        // chunk 0..3 (16B each)

#pragma unroll
    for (int mi = 0; mi < 4; mi++)
#pragma unroll
        for (int ni = 0; ni < 4; ni++)
#pragma unroll
            for (int j = 0; j < 4; j++) acc[mi][ni][j] = 0.f;

    auto load_stage = [&](int kt, int buf) {
        const int k0 = kt * KSTG;
        uint32_t base = sb + (uint32_t)buf * SWORDS * 4;
#pragma unroll
        for (int t = 0; t < 4; t++) {
            const __nv_bfloat16* src = srcs[t] + k0;
            uint32_t db = base + (uint32_t)t * TWORDS * 4;
#pragma unroll
            for (int q = 0; q < 2; q++) {
                int r = r_ld + q * 64;
                cp16(db + (uint32_t)(r * PITCH + c_ld * 4) * 4,
                     src + (size_t)r * DD + c_ld * 8);
            }
        }
        CP_COMMIT();
    };

    load_stage(0, 0);

    const int awoff = (warpM * 64 + l16) * PITCH;
    const int bwoff = (warpN * 32 + bkey) * PITCH + bch * 4;

    for (int kt = 0; kt < NSTG; kt++) {
        int buf = kt & 1;
        if (kt + 1 < NSTG) {
            load_stage(kt + 1, buf ^ 1);
            CP_WAIT(1);
        } else {
            CP_WAIT(0);
        }
        __syncthreads();

        uint32_t tb = sb + (uint32_t)buf * SWORDS * 4;
        uint32_t pAh = tb;
        uint32_t pAl = tb + TWORDS * 4;
        uint32_t pBh = tb + 2 * TWORDS * 4;
        uint32_t pBl = tb + 3 * TWORDS * 4;

#pragma unroll
        for (int ks = 0; ks < 2; ks++) {
            uint32_t ah[4][4], al[4][4], bh[4][2], bl[4][2];
#pragma unroll
            for (int mi = 0; mi < 4; mi++) {
                uint32_t wo = (uint32_t)(awoff + mi * 16 * PITCH + ks * 8 + lh2 * 4) * 4;
                ldsm_x4(ah[mi], pAh + wo);
                ldsm_x4(al[mi], pAl + wo);
            }
#pragma unroll
            for (int jj = 0; jj < 2; jj++) {
                uint32_t wo = (uint32_t)(bwoff + jj * 16 * PITCH + ks * 8) * 4;
                uint32_t r[4];
                ldsm_x4(r, pBh + wo);
                bh[2*jj][0] = r[0]; bh[2*jj][1] = r[1];
                bh[2*jj+1][0] = r[2]; bh[2*jj+1][1] = r[3];
                ldsm_x4(r, pBl + wo);
                bl[2*jj][0] = r[0]; bl[2*jj][1] = r[1];
                bl[2*jj+1][0] = r[2]; bl[2*jj+1][1] = r[3];
            }
#pragma unroll
            for (int mi = 0; mi < 4; mi++)
#pragma unroll
                for (int ni = 0; ni < 4; ni++) {
                    mma16816(acc[mi][ni], ah[mi], bh[ni]);
                    mma16816(acc[mi][ni], ah[mi], bl[ni]);
                    mma16816(acc[mi][ni], al[mi], bh[ni]);
                }
        }
        __syncthreads();
    }
}

// ---------------- fused QKV projection (z = 0:Q, 1:K, 2:V) -------------------
__global__ void __launch_bounds__(256, 2) gemm_qkv_kernel(
    const __nv_bfloat16* __restrict__ Xh, const __nv_bfloat16* __restrict__ Xl,
    const __nv_bfloat16* __restrict__ Wh, const __nv_bfloat16* __restrict__ Wl,
    __nv_bfloat16* __restrict__ Qh, __nv_bfloat16* __restrict__ Ql,
    __nv_bfloat16* __restrict__ Kh, __nv_bfloat16* __restrict__ Kl,
    __nv_bfloat16* __restrict__ Vh, __nv_bfloat16* __restrict__ Vl)
{
    extern __shared__ uint32_t sm4[];
    uint32_t sb = smem_u32(sm4);
    const int z = blockIdx.z;
    const int row0 = blockIdx.y * 128;
    const int col0 = blockIdx.x * 128;
    const __nv_bfloat16* Bh = Wh + (size_t)z * DD * DD + (size_t)col0 * DD;
    const __nv_bfloat16* Bl = Wl + (size_t)z * DD * DD + (size_t)col0 * DD;

    float acc[4][4][4];
    gemm_core(Xh + (size_t)row0 * DD, Xl + (size_t)row0 * DD, Bh, Bl, sb, acc);

    __nv_bfloat16* Oh = (z == 0) ? Qh : (z == 1) ? Kh : Vh;
    __nv_bfloat16* Ol = (z == 0) ? Ql : (z == 1) ? Kl : Vl;
    const bool dorope = (z < 2);

    const int lane = threadIdx.x & 31, wid = threadIdx.x >> 5;
    const int warpM = wid & 1, warpN = wid >> 1;
    const int g = lane >> 2, t4 = lane & 3;
    const int h = blockIdx.x;

#pragma unroll
    for (int mi = 0; mi < 4; mi++) {
#pragma unroll
        for (int ni = 0; ni < 4; ni++) {
            int m0 = row0 + warpM * 64 + mi * 16 + g;
            int d  = warpN * 32 + ni * 8 + t4 * 2;
            float v0 = acc[mi][ni][0], v1 = acc[mi][ni][1];
            float v2 = acc[mi][ni][2], v3 = acc[mi][ni][3];
            int b0i = m0 >> 11, s0 = m0 & 2047;
            int b1i = (m0 + 8) >> 11, s1 = (m0 + 8) & 2047;
            if (dorope) {
                int p = d >> 1;
                float c0 = g_cos[s0 * 64 + p], sn0 = g_sin[s0 * 64 + p];
                float c1 = g_cos[s1 * 64 + p], sn1 = g_sin[s1 * 64 + p];
                float r0 = v0 * c0 - v1 * sn0, r1 = v0 * sn0 + v1 * c0;
                float r2 = v2 * c1 - v3 * sn1, r3 = v2 * sn1 + v3 * c1;
                v0 = r0; v1 = r1; v2 = r2; v3 = r3;
            }
            size_t i0 = ((size_t)(b0i * HH + h) * SS + s0) * HD + d;
            size_t i1 = ((size_t)(b1i * HH + h) * SS + s1) * HD + d;
            uint32_t hp, lp;
            split2(v0, v1, hp, lp);
            *(uint32_t*)&Oh[i0] = hp;
            *(uint32_t*)&Ol[i0] = lp;
            split2(v2, v3, hp, lp);
            *(uint32_t*)&Oh[i1] = hp;
            *(uint32_t*)&Ol[i1] = lp;
        }
    }
}

// ---------------- output projection + bias -----------------------------------
__global__ void __launch_bounds__(256, 2) gemm_o_kernel(
    const __nv_bfloat16* __restrict__ Ah, const __nv_bfloat16* __restrict__ Al,
    const __nv_bfloat16* __restrict__ Bh, const __nv_bfloat16* __restrict__ Bl,
    const float* __restrict__ bias, float* __restrict__ C)
{
    extern __shared__ uint32_t sm4[];
    uint32_t sb = smem_u32(sm4);
    const int row0 = blockIdx.y * 128;
    const int col0 = blockIdx.x * 128;

    float acc[4][4][4];
    gemm_core(Ah + (size_t)row0 * DD, Al + (size_t)row0 * DD,
              Bh + (size_t)col0 * DD, Bl + (size_t)col0 * DD, sb, acc);

    const int lane = threadIdx.x & 31, wid = threadIdx.x >> 5;
    const int warpM = wid & 1, warpN = wid >> 1;
    const int g = lane >> 2, t4 = lane & 3;

#pragma unroll
    for (int mi = 0; mi < 4; mi++) {
#pragma unroll
        for (int ni = 0; ni < 4; ni++) {
            int m0 = row0 + warpM * 64 + mi * 16 + g;
            int n  = col0 + warpN * 32 + ni * 8 + t4 * 2;
            float b0 = bias[n], b1 = bias[n + 1];
            *(float2*)&C[(size_t)m0 * DD + n] =
                make_float2(acc[mi][ni][0] + b0, acc[mi][ni][1] + b1);
            *(float2*)&C[(size_t)(m0 + 8) * DD + n] =
                make_float2(acc[mi][ni][2] + b0, acc[mi][ni][3] + b1);
        }
    }
}

// ---------------- HMMA flash attention (unchanged from R5) -------------------
#define AT_QH 0
#define AT_QL 9216
#define AT_KV 18432
#define AT_STG 18432
#define ATT_SMEM (55296*4)   // 221184 B

__global__ void __launch_bounds__(256, 1) attn_mma_kernel(
    const __nv_bfloat16* __restrict__ Qh, const __nv_bfloat16* __restrict__ Ql,
    const __nv_bfloat16* __restrict__ Kh, const __nv_bfloat16* __restrict__ Kl,
    const __nv_bfloat16* __restrict__ Vh, const __nv_bfloat16* __restrict__ Vl,
    __nv_bfloat16* __restrict__ CH, __nv_bfloat16* __restrict__ CL)
{
    extern __shared__ uint32_t smw[];
    uint32_t sb = smem_u32(smw);
    const int tid = threadIdx.x, lane = tid & 31, w = tid >> 5;
    const int g = lane >> 2, t4 = lane & 3;
    const int bh = blockIdx.y;
    const int bidx = bh / HH, hidx = bh % HH;
    const int qb = gridDim.x - 1 - blockIdx.x;
    const int q0 = qb * 128;
    const int nkt = qb * 2 + 2;
    const size_t hb = (size_t)bh * SS * HD;

    const int l16 = lane & 15, lh2 = lane >> 4;
    const int bkey = (lane & 7) | ((lane >> 4) << 3);
    const int bch  = (lane >> 3) & 1;
    const int vkey = (lane & 7) | (((lane >> 3) & 1) << 3);
    const int vch  = lane >> 4;

    {
        const __nv_bfloat16* qs0 = Qh + hb + (size_t)q0 * HD;
        const __nv_bfloat16* qs1 = Ql + hb + (size_t)q0 * HD;
#pragma unroll
        for (int i = 0; i < 16; i++) {
            int idx = tid + i * 256;
            int pl = idx >> 11;
            int c = idx & 2047;
            int row = c >> 4;
            int piece = c & 15;
            uint32_t dw = (pl ? AT_QL : AT_QH) + (piece >> 3) * 4608
                        + row * 36 + (piece & 7) * 4;
            cp16(sb + dw * 4, (pl ? qs1 : qs0) + (size_t)row * HD + piece * 8);
        }
    }
    const __nv_bfloat16* kvsrc[4] = {Kh + hb, Kl + hb, Vh + hb, Vl + hb};
    auto load_kv = [&](int kt, int buf) {
        int k0 = kt * 64;
#pragma unroll
        for (int i = 0; i < 16; i++) {
            int idx = tid + i * 256;
            int pl = idx >> 10;
            int c = idx & 1023;
            int row = c >> 4;
            int piece = c & 15;
            uint32_t dw = AT_KV + buf * AT_STG + pl * 4608 + (piece >> 3) * 2304
                        + row * 36 + (piece & 7) * 4;
            cp16(sb + dw * 4, kvsrc[pl] + (size_t)(k0 + row) * HD + piece * 8);
        }
    };
    load_kv(0, 0); CP_COMMIT();
    load_kv(1, 1); CP_COMMIT();

    float ofr[16][4];
#pragma unroll
    for (int i = 0; i < 16; i++)
#pragma unroll
        for (int j = 0; j < 4; j++) ofr[i][j] = 0.f;
    float m0 = -1e30f, m1 = -1e30f, l0 = 0.f, l1 = 0.f;
    const float scale = 0.08838834764831845f;

    const uint32_t qwoff = (uint32_t)(w * 16 + l16) * 36;
    const int rowg = q0 + w * 16 + g;

    for (int kt = 0; kt < nkt; kt++) {
        if (kt + 1 < nkt) { CP_WAIT(1); } else { CP_WAIT(0); }
        __syncthreads();
        int buf = kt & 1;
        uint32_t stg = AT_KV + (uint32_t)buf * AT_STG;
        bool active = !(kt == nkt - 1 && w < 4);

        if (active) {
            float sf[8][4];
#pragma unroll
            for (int n = 0; n < 8; n++)
#pragma unroll
                for (int c = 0; c < 4; c++) sf[n][c] = 0.f;

#pragma unroll
            for (int ks = 0; ks < 8; ks++) {
                uint32_t qwo = ((uint32_t)(ks >> 2) * 4608 + qwoff + (ks & 3) * 8 + lh2 * 4) * 4;
                uint32_t qh4[4], ql4[4];
                ldsm_x4(qh4, sb + AT_QH * 4 + qwo);
                ldsm_x4(ql4, sb + AT_QL * 4 + qwo);
                uint32_t khf[8][2], klf[8][2];
#pragma unroll
                for (int j = 0; j < 4; j++) {
                    uint32_t kwo = (stg + (uint32_t)(ks >> 2) * 2304
                                  + (uint32_t)(j * 16 + bkey) * 36 + (ks & 3) * 8 + bch * 4) * 4;
                    uint32_t r[4];
                    ldsm_x4(r, sb + kwo);
                    khf[2*j][0] = r[0]; khf[2*j][1] = r[1];
                    khf[2*j+1][0] = r[2]; khf[2*j+1][1] = r[3];
                    ldsm_x4(r, sb + kwo + 4608 * 4);
                    klf[2*j][0] = r[0]; klf[2*j][1] = r[1];
                    klf[2*j+1][0] = r[2]; klf[2*j+1][1] = r[3];
                }
#pragma unroll
                for (int n = 0; n < 8; n++) {
                    mma16816(sf[n], qh4, khf[n]);
                    mma16816(sf[n], qh4, klf[n]);
                    mma16816(sf[n], ql4, khf[n]);
                }
            }

            int k0 = kt * 64;
            bool domask = (kt >= nkt - 2);
            float mx0 = -1e30f, mx1 = -1e30f;
#pragma unroll
            for (int n = 0; n < 8; n++) {
#pragma unroll
                for (int c = 0; c < 4; c++) {
                    float v = sf[n][c] * scale;
                    if (domask) {
                        int col = k0 + n * 8 + 2 * t4 + (c & 1);
                        int row = rowg + ((c >> 1) << 3);
                        if (col > row) v = -1e30f;
                    }
                    sf[n][c] = v;
                    if (c < 2) mx0 = fmaxf(mx0, v); else mx1 = fmaxf(mx1, v);
                }
            }
            mx0 = fmaxf(mx0, __shfl_xor_sync(0xffffffffu, mx0, 1));
            mx0 = fmaxf(mx0, __shfl_xor_sync(0xffffffffu, mx0, 2));
            mx1 = fmaxf(mx1, __shfl_xor_sync(0xffffffffu, mx1, 1));
            mx1 = fmaxf(mx1, __shfl_xor_sync(0xffffffffu, mx1, 2));
            float mn0 = fmaxf(m0, mx0), mn1 = fmaxf(m1, mx1);
            float a0 = fexp(m0 - mn0), a1 = fexp(m1 - mn1);
            m0 = mn0; m1 = mn1;
            float s0 = 0.f, s1 = 0.f;
#pragma unroll
            for (int n = 0; n < 8; n++) {
                sf[n][0] = fexp(sf[n][0] - mn0); s0 += sf[n][0];
                sf[n][1] = fexp(sf[n][1] - mn0); s0 += sf[n][1];
                sf[n][2] = fexp(sf[n][2] - mn1); s1 += sf[n][2];
                sf[n][3] = fexp(sf[n][3] - mn1); s1 += sf[n][3];
            }
            s0 += __shfl_xor_sync(0xffffffffu, s0, 1);
            s0 += __shfl_xor_sync(0xffffffffu, s0, 2);
            s1 += __shfl_xor_sync(0xffffffffu, s1, 1);
            s1 += __shfl_xor_sync(0xffffffffu, s1, 2);
            l0 = l0 * a0 + s0;
            l1 = l1 * a1 + s1;
#pragma unroll
            for (int nc = 0; nc < 16; nc++) {
                ofr[nc][0] *= a0; ofr[nc][1] *= a0;
                ofr[nc][2] *= a1; ofr[nc][3] *= a1;
            }

            uint32_t ph[4][4], plo[4][4];
#pragma unroll
            for (int kb = 0; kb < 4; kb++) {
                split2(sf[2*kb][0],   sf[2*kb][1],   ph[kb][0], plo[kb][0]);
                split2(sf[2*kb][2],   sf[2*kb][3],   ph[kb][1], plo[kb][1]);
                split2(sf[2*kb+1][0], sf[2*kb+1][1], ph[kb][2], plo[kb][2]);
                split2(sf[2*kb+1][2], sf[2*kb+1][3], ph[kb][3], plo[kb][3]);
            }

#pragma unroll
            for (int kb = 0; kb < 4; kb++) {
                uint32_t krow = (uint32_t)(kb * 16 + vkey) * 36;
#pragma unroll
                for (int jj = 0; jj < 8; jj++) {
                    int cj = jj * 2 + vch;
                    uint32_t vwo = (stg + 9216u + (uint32_t)(cj >> 3) * 2304
                                  + krow + (uint32_t)(cj & 7) * 4) * 4;
                    uint32_t rv[4], rl[4];
                    ldsm_x4_t(rv, sb + vwo);
                    ldsm_x4_t(rl, sb + vwo + 4608 * 4);
                    mma2(ofr[2*jj],   ph[kb], rv[0], rv[1]);
                    mma2(ofr[2*jj],   ph[kb], rl[0], rl[1]);
                    mma2(ofr[2*jj],   plo[kb], rv[0], rv[1]);
                    mma2(ofr[2*jj+1], ph[kb], rv[2], rv[3]);
                    mma2(ofr[2*jj+1], ph[kb], rl[2], rl[3]);
                    mma2(ofr[2*jj+1], plo[kb], rv[2], rv[3]);
                }
            }
        }
        __syncthreads();
        if (kt + 2 < nkt) { load_kv(kt + 2, buf); CP_COMMIT(); }
    }

    float i0 = 1.f / l0, i1 = 1.f / l1;
    int r0 = q0 + w * 16 + g, r1 = r0 + 8;
    size_t base0 = ((size_t)(bidx * SS + r0)) * DD + hidx * HD;
    size_t base1 = ((size_t)(bidx * SS + r1)) * DD + hidx * HD;
#pragma unroll
    for (int nc = 0; nc < 16; nc++) {
        int d = nc * 8 + 2 * t4;
        uint32_t hp, lp;
        split2(ofr[nc][0] * i0, ofr[nc][1] * i0, hp, lp);
        *(uint32_t*)&CH[base0 + d] = hp;
        *(uint32_t*)&CL[base0 + d] = lp;
        split2(ofr[nc][2] * i1, ofr[nc][3] * i1, hp, lp);
        *(uint32_t*)&CH[base1 + d] = hp;
        *(uint32_t*)&CL[base1 + d] = lp;
    }
}

// ---------------------------------------------------------------------------
extern "C" void kernel_launch(void* const* d_in, const int* in_sizes, int n_in,
                              void* d_out, int out_size)
{
    const float* x  = (const float*)d_in[0];
    const float* wq = (const float*)d_in[1];
    const float* wk = (const float*)d_in[2];
    const float* wv = (const float*)d_in[3];
    const float* wo = (const float*)d_in[4];
    const float* bo = (const float*)d_in[5];
    float* out = (float*)d_out;

    __nv_bfloat16 *qh, *ql, *kh, *kl, *vh, *vl, *xh, *xl, *wh, *wl, *ch, *cl;
    cudaGetSymbolAddress((void**)&qh, g_qh);
    cudaGetSymbolAddress((void**)&ql, g_ql);
    cudaGetSymbolAddress((void**)&kh, g_kh);
    cudaGetSymbolAddress((void**)&kl, g_kl);
    cudaGetSymbolAddress((void**)&vh, g_vh);
    cudaGetSymbolAddress((void**)&vl, g_vl);
    cudaGetSymbolAddress((void**)&xh, g_xh);
    cudaGetSymbolAddress((void**)&xl, g_xl);
    cudaGetSymbolAddress((void**)&wh, g_wh);
    cudaGetSymbolAddress((void**)&wl, g_wl);
    cudaGetSymbolAddress((void**)&ch, g_ch);
    cudaGetSymbolAddress((void**)&cl, g_cl);

    // launch order (for ncu -s 5 -c 1: 6th launch = attention)
    rope_table_kernel<<<(SS * 64 + 255) / 256, 256>>>();                      // 1

    int n4 = MM * DD / 4;
    cvt_split_kernel<<<(n4 + 255) / 256, 256>>>(x, xh, xl, n4);               // 2
    int w4 = DD * DD / 4;
    cvt_split2_kernel<<<(2 * w4 + 255) / 256, 256>>>(                         // 3
        wq, wk, wh, wl, wh + (size_t)1 * DD * DD, wl + (size_t)1 * DD * DD, w4);
    cvt_split2_kernel<<<(2 * w4 + 255) / 256, 256>>>(                         // 4
        wv, wo, wh + (size_t)2 * DD * DD, wl + (size_t)2 * DD * DD,
        wh + (size_t)3 * DD * DD, wl + (size_t)3 * DD * DD, w4);

    cudaFuncSetAttribute(gemm_qkv_kernel, cudaFuncAttributeMaxDynamicSharedMemorySize, GEMM_SMEM);
    cudaFuncSetAttribute(gemm_o_kernel,   cudaFuncAttributeMaxDynamicSharedMemorySize, GEMM_SMEM);
    cudaFuncSetAttribute(attn_mma_kernel, cudaFuncAttributeMaxDynamicSharedMemorySize, ATT_SMEM);

    gemm_qkv_kernel<<<dim3(DD / 128, MM / 128, 3), 256, GEMM_SMEM>>>(         // 5
        xh, xl, wh, wl, qh, ql, kh, kl, vh, vl);

    attn_mma_kernel<<<dim3(SS / 128, BB * HH), 256, ATT_SMEM>>>(              // 6
        qh, ql, kh, kl, vh, vl, ch, cl);

    gemm_o_kernel<<<dim3(DD / 128, MM / 128), 256, GEMM_SMEM>>>(              // 7
        ch, cl, wh + (size_t)3 * DD * DD, wl + (size_t)3 * DD * DD, bo, out);
}